// round 8
// baseline (speedup 1.0000x reference)
#include <cuda_runtime.h>
#include <cstdint>

// Problem constants
#define Bn 8
#define Tn 256
#define Un 64
#define Hn 512
#define Fn 1024

// tf32-prerounded copies (no cudaMalloc -> device globals).
// g_act: audio rows [0, 2048), label rows [2048, 2560).
__device__ float g_act[(Bn * Tn + Bn * Un) * Hn];  // 5 MB
__device__ float g_w[2 * Hn * Fn];                 // 4 MB

__device__ __forceinline__ float to_tf32(float x) {
    float r;
    asm("cvt.rna.tf32.f32 %0, %1;" : "=f"(r) : "f"(x));
    return r;
}

// ---------------------------------------------------------------------------
// Prep: round all GEMM operands to tf32 (RNA) once.
// ---------------------------------------------------------------------------
__global__ __launch_bounds__(256)
void prep_kernel(const float* __restrict__ audio,
                 const float* __restrict__ label,
                 const float* __restrict__ W)
{
    const int NA = Bn * Tn * Hn / 4;   // 262144 float4
    const int NL = Bn * Un * Hn / 4;   // 65536
    int i = blockIdx.x * 256 + threadIdx.x;
    const float4* src;
    float4* dst;
    if (i < NA)           { src = (const float4*)audio + i;         dst = (float4*)g_act + i; }
    else if (i < NA + NL) { src = (const float4*)label + (i - NA);  dst = (float4*)g_act + i; }
    else                  { src = (const float4*)W + (i - NA - NL); dst = (float4*)g_w + (i - NA - NL); }
    float4 v = *src;
    float4 o = { to_tf32(v.x), to_tf32(v.y), to_tf32(v.z), to_tf32(v.w) };
    *dst = o;
}

// ---------------------------------------------------------------------------
// Fused kernel. CTA = (b, 64 t-rows, 64 f-cols). 512 CTAs, ALL resident (4/SM).
// GEMM: M=128 (rows 0..63 audio t, 64..127 label u), N=64, K=512, BK=16.
//   Warps 0-3 audio (Wa half), warps 4-7 label (Wl half); per role 2(M)x2(N),
//   warp tile 32x32, tf32 m16n8k8, 2-stage cp.async pipeline (32 iters).
// Epilogue: stage C (128 x 64, pitch 68) in SMEM (union over GEMM stages),
//   then stream out[t,u,f] = Ca[t,f] + Cl[u,f] (+bias) with .cs float4 stores.
// SMEM stage (floats): AL 128x20 @0 (2560), Wa 16x72 @2560, Wl @3712.
// Stage = 4864 floats; 2 stages = 38912 B. C tile (8704 fl = 34816 B) unions.
// ---------------------------------------------------------------------------
#define STG_FL 4864
#define SMEM_BYTES 38912

extern __shared__ float smem[];

#define CPA16(dst, src) \
    asm volatile("cp.async.cg.shared.global [%0], [%1], 16;" :: "r"(dst), "l"(src))

__global__ __launch_bounds__(256, 4)
void joint_fused(const float* __restrict__ bias, float* __restrict__ out)
{
    const int fb = blockIdx.x;            // 0..15  (f tile of 64)
    const int tb = blockIdx.y;            // 0..3   (t tile of 64)
    const int b  = blockIdx.z;            // 0..7

    const int tid  = threadIdx.x;
    const int warp = tid >> 5;
    const int lane = tid & 31;
    const int role = warp >> 2;           // 0 = audio, 1 = label
    const int w4   = warp & 3;
    const int wm   = w4 >> 1;             // 0..1 (M)
    const int wn_  = w4 & 1;              // 0..1 (N)
    const int g    = lane >> 2;           // 0..7
    const int tig  = lane & 3;            // 0..3

    const uint32_t sb = (uint32_t)__cvta_generic_to_shared(smem);

    // ---- cp.async coordinates ----
    // Audio: 64 rows x 4 float4 (BK=16) = 256 float4 -> 1/thread. Label same.
    const int rA = tid >> 2;              // 0..63
    const int cA = tid & 3;               // float4 index along K
    const float* a_src = g_act + (size_t)(b * Tn + tb * 64 + rA) * Hn + cA * 4;
    // label row = 2048 + b*64 + rA; uniform offset from audio row:
    const int loff = ((Bn * Tn) + b * Un - (b * Tn + tb * 64)) * Hn;  // uniform
    const uint32_t dA = (uint32_t)(rA * 20 + cA * 4) * 4;
    const uint32_t dL = dA + 5120u;       // label rows at +64*20 floats

    // W: per half 16 rows x 16 float4 = 256 -> 1/thread.
    const int kr = tid >> 4;              // 0..15
    const int cw = tid & 15;              // float4 along N(64)
    const float* w_src = g_w + (size_t)kr * Fn + fb * 64 + cw * 4;
    const uint32_t dWa = (uint32_t)(2560 + kr * 72 + cw * 4) * 4;
    const uint32_t dWl = dWa + 1152u * 4;
    const int WOFF = Hn * Fn;             // Wl is +512 rows

    float c[2][4][4];
#pragma unroll
    for (int mt = 0; mt < 2; mt++)
#pragma unroll
        for (int nt = 0; nt < 4; nt++)
#pragma unroll
            for (int r = 0; r < 4; r++) c[mt][nt][r] = 0.0f;

    auto issue = [&](int s) {
        const uint32_t st = sb + (uint32_t)s * (STG_FL * 4);
        CPA16(st + dA, a_src);
        CPA16(st + dL, a_src + loff);
        CPA16(st + dWa, w_src);
        CPA16(st + dWl, w_src + WOFF);
        asm volatile("cp.async.commit_group;");
        a_src += 16;
        w_src += 16 * Fn;
    };

    issue(0);

#pragma unroll 1
    for (int it = 0; it < 32; ++it) {
        const int s = it & 1;
        if (it < 31) {
            issue(s ^ 1);
            asm volatile("cp.async.wait_group 1;");
        } else {
            asm volatile("cp.async.wait_group 0;");
        }
        __syncthreads();

        const float* at = smem + s * STG_FL;                      // AL 128x20
        const float* wt = smem + s * STG_FL + 2560 + role * 1152; // W half 16x72

#pragma unroll
        for (int ks = 0; ks < 2; ks++) {
            const int k0 = ks * 8 + tig;
            uint32_t af[2][4], bf[4][2];
#pragma unroll
            for (int mt = 0; mt < 2; mt++) {
                const int arow = role * 64 + wm * 32 + mt * 16 + g;
                af[mt][0] = __float_as_uint(at[arow * 20 + k0]);
                af[mt][1] = __float_as_uint(at[(arow + 8) * 20 + k0]);
                af[mt][2] = __float_as_uint(at[arow * 20 + k0 + 4]);
                af[mt][3] = __float_as_uint(at[(arow + 8) * 20 + k0 + 4]);
            }
#pragma unroll
            for (int nt = 0; nt < 4; nt++) {
                const int n0 = wn_ * 32 + nt * 8 + g;
                bf[nt][0] = __float_as_uint(wt[k0 * 72 + n0]);
                bf[nt][1] = __float_as_uint(wt[(k0 + 4) * 72 + n0]);
            }
#pragma unroll
            for (int mt = 0; mt < 2; mt++)
#pragma unroll
                for (int nt = 0; nt < 4; nt++) {
                    asm volatile(
                        "mma.sync.aligned.m16n8k8.row.col.f32.tf32.tf32.f32 "
                        "{%0,%1,%2,%3}, {%4,%5,%6,%7}, {%8,%9}, {%0,%1,%2,%3};"
                        : "+f"(c[mt][nt][0]), "+f"(c[mt][nt][1]),
                          "+f"(c[mt][nt][2]), "+f"(c[mt][nt][3])
                        : "r"(af[mt][0]), "r"(af[mt][1]),
                          "r"(af[mt][2]), "r"(af[mt][3]),
                          "r"(bf[nt][0]), "r"(bf[nt][1]));
                }
        }
        __syncthreads();
    }

    // ---- Stage C into SMEM: 128 rows x 64 f, pitch 68 floats ----
    float* Cs = smem;
#pragma unroll
    for (int nt = 0; nt < 4; nt++) {
        const int col = wn_ * 32 + nt * 8 + 2 * tig;
        float b0 = 0.0f, b1 = 0.0f;
        if (role == 0) {
            b0 = bias[fb * 64 + col];
            b1 = bias[fb * 64 + col + 1];
        }
#pragma unroll
        for (int mt = 0; mt < 2; mt++) {
            const int row = role * 64 + wm * 32 + mt * 16 + g;
            float2 v0 = { c[mt][nt][0] + b0, c[mt][nt][1] + b1 };
            float2 v1 = { c[mt][nt][2] + b0, c[mt][nt][3] + b1 };
            *(float2*)&Cs[row * 68 + col]       = v0;
            *(float2*)&Cs[(row + 8) * 68 + col] = v1;
        }
    }
    __syncthreads();

    // ---- Broadcast store ----
    // Per (t,u) row: 64 f = 16 float4. Warp w owns u in [w*8, w*8+8).
    // lane: fi = lane&15 (float4 within row), uh = lane>>4 (0..1).
    const float4* Cs4 = (const float4*)smem;   // pitch 17 float4
    float4* out4 = (float4*)out;
    const int fi = lane & 15;
    const int uh = lane >> 4;

    float4 lreg[4];
#pragma unroll
    for (int i = 0; i < 4; i++) {
        const int u = warp * 8 + i * 2 + uh;
        lreg[i] = Cs4[(64 + u) * 17 + fi];
    }

    const size_t row0 = ((size_t)(b * Tn + tb * 64) * Un) * (Fn / 4) + fb * 16 + fi;

#pragma unroll 2
    for (int tt = 0; tt < 64; ++tt) {
        const float4 a = Cs4[tt * 17 + fi];          // broadcast across uh
        const size_t tbase = row0 + (size_t)tt * Un * (Fn / 4);
#pragma unroll
        for (int i = 0; i < 4; i++) {
            const int u = warp * 8 + i * 2 + uh;
            float4 v = { a.x + lreg[i].x, a.y + lreg[i].y,
                         a.z + lreg[i].z, a.w + lreg[i].w };
            __stcs(out4 + tbase + (size_t)u * (Fn / 4), v);
        }
    }
}

// ---------------------------------------------------------------------------
extern "C" void kernel_launch(void* const* d_in, const int* in_sizes, int n_in,
                              void* d_out, int out_size)
{
    const float* audio = (const float*)d_in[0];   // (8,256,512)
    const float* label = (const float*)d_in[1];   // (8,64,512)
    const float* W     = (const float*)d_in[2];   // (1024,1024)
    const float* bias  = (const float*)d_in[3];   // (1024,)
    float* out = (float*)d_out;                   // (8,256,64,1024)

    cudaFuncSetAttribute(joint_fused,
                         cudaFuncAttributeMaxDynamicSharedMemorySize, SMEM_BYTES);

    prep_kernel<<<2304, 256>>>(audio, label, W);
    joint_fused<<<dim3(16, 4, 8), 256, SMEM_BYTES>>>(bias, out);
}

// round 11
// speedup vs baseline: 1.1472x; 1.1472x over previous
#include <cuda_runtime.h>
#include <cstdint>

// Problem constants
#define Bn 8
#define Tn 256
#define Un 64
#define Hn 512
#define Fn 1024

// tf32-prerounded copies (no cudaMalloc -> device globals).
// g_act: audio rows [0, 2048), label rows [2048, 2560).
__device__ float g_act[(Bn * Tn + Bn * Un) * Hn];  // 5 MB
__device__ float g_w[2 * Hn * Fn];                 // 4 MB

__device__ __forceinline__ float to_tf32(float x) {
    float r;
    asm("cvt.rna.tf32.f32 %0, %1;" : "=f"(r) : "f"(x));
    return r;
}

// ---------------------------------------------------------------------------
// Prep: round all GEMM operands to tf32 (RNA) once.
// ---------------------------------------------------------------------------
__global__ __launch_bounds__(256)
void prep_kernel(const float* __restrict__ audio,
                 const float* __restrict__ label,
                 const float* __restrict__ W)
{
    const int NA = Bn * Tn * Hn / 4;   // 262144 float4
    const int NL = Bn * Un * Hn / 4;   // 65536
    int i = blockIdx.x * 256 + threadIdx.x;
    const float4* src;
    float4* dst;
    if (i < NA)           { src = (const float4*)audio + i;         dst = (float4*)g_act + i; }
    else if (i < NA + NL) { src = (const float4*)label + (i - NA);  dst = (float4*)g_act + i; }
    else                  { src = (const float4*)W + (i - NA - NL); dst = (float4*)g_w + (i - NA - NL); }
    float4 v = *src;
    float4 o = { to_tf32(v.x), to_tf32(v.y), to_tf32(v.z), to_tf32(v.w) };
    *dst = o;
}

// ---------------------------------------------------------------------------
// Warp-specialized persistent fused kernel.
// 296 CTAs (2/SM), 512 threads: warps 0-7 GEMM (0-3 audio, 4-7 label),
// warps 8-15 store. 1024 tiles of (b, 64 t, 32 f), striped by CTA.
// Per tile GEMM: M=128 (64 audio t + 64 label u), N=32, K=512, BK=32,
//   warp tile 32x16, tf32 m16n8k8, 2-stage cp.async (16 iters, bar 1).
// Handoff: single C buffer (128 x 32, pitch 40) with two rendezvous
//   bar.sync barriers (full fence semantics on both sides):
//     H1 (id 2, 512): consumer finished reading C   (skipped: first/last)
//     H2 (id 3, 512): producer published C
//   Store of tile i overlaps GEMM of tile i+1.
// SMEM: stages 2 x 7168 fl (57344 B) + C 5120 fl (20480 B) = 77824 B.
// ---------------------------------------------------------------------------
#define STG_FL 7168
#define C_OFF  14336            // float offset of C buffer
#define SMEM_BYTES 77824
#define NTILES 1024
#define NCTAS  296

extern __shared__ float smem[];

#define CPA16(dst, src) \
    asm volatile("cp.async.cg.shared.global [%0], [%1], 16;" :: "r"(dst), "l"(src))
#define BAR_SYNC(id, cnt) \
    asm volatile("bar.sync %0, %1;" :: "r"(id), "r"(cnt) : "memory")

__global__ __launch_bounds__(512, 2)
void joint_fused(const float* __restrict__ bias, float* __restrict__ out)
{
    const int tid  = threadIdx.x;
    const int warp = tid >> 5;
    const int lane = tid & 31;
    const uint32_t sb = (uint32_t)__cvta_generic_to_shared(smem);

    if (warp < 8) {
        // ===================== GEMM group (256 threads) =====================
        const int role = warp >> 2;           // 0 = audio, 1 = label
        const int w4   = warp & 3;
        const int wm   = w4 >> 1;
        const int wn_  = w4 & 1;
        const int g    = lane >> 2;
        const int tig  = lane & 3;

        // cp.async fixed per-thread coordinates
        int rA[2], cA[2];
        uint32_t dA[2];
#pragma unroll
        for (int i = 0; i < 2; i++) {
            int id = tid + i * 256;
            rA[i] = id >> 3;  cA[i] = id & 7;
            dA[i] = (uint32_t)(rA[i] * 36 + cA[i] * 4) * 4;
        }
        const int kr = tid >> 3;
        const int cw = tid & 7;
        const uint32_t dWa = (uint32_t)(4608 + kr * 40 + cw * 4) * 4;
        const uint32_t dWl = dWa + 1280u * 4;
        const int WOFF = Hn * Fn;

        bool first = true;
        for (int idx = blockIdx.x; idx < NTILES; idx += NCTAS) {
            const int fb = idx & 31;
            const int tb = (idx >> 5) & 3;
            const int b  = idx >> 7;

            const float* a0 = g_act + (size_t)(b * Tn + tb * 64) * Hn;
            const float* l0 = g_act + (size_t)(Bn * Tn + b * Un) * Hn;

            float c[2][2][4];
#pragma unroll
            for (int mt = 0; mt < 2; mt++)
#pragma unroll
                for (int nt = 0; nt < 2; nt++)
#pragma unroll
                    for (int r = 0; r < 4; r++) c[mt][nt][r] = 0.0f;

            const float* a_src[2];
            const float* l_src[2];
#pragma unroll
            for (int i = 0; i < 2; i++) {
                a_src[i] = a0 + (size_t)rA[i] * Hn + cA[i] * 4;
                l_src[i] = l0 + (size_t)rA[i] * Hn + cA[i] * 4;
            }
            // FIX (round 9/10 bug): include the per-thread cw*4 column offset.
            const float* wa_src = g_w + (size_t)kr * Fn + fb * 32 + cw * 4;
            const float* wl_src = wa_src + WOFF;

            auto issue = [&](int s) {
                const uint32_t st = sb + (uint32_t)s * (STG_FL * 4);
#pragma unroll
                for (int i = 0; i < 2; i++) {
                    CPA16(st + dA[i], a_src[i]);
                    CPA16(st + dA[i] + 9216u, l_src[i]);
                }
                CPA16(st + dWa, wa_src);
                CPA16(st + dWl, wl_src);
                asm volatile("cp.async.commit_group;");
#pragma unroll
                for (int i = 0; i < 2; i++) { a_src[i] += 32; l_src[i] += 32; }
                wa_src += 32 * Fn;  wl_src += 32 * Fn;
            };

            issue(0);

#pragma unroll 1
            for (int it = 0; it < 16; ++it) {
                const int s = it & 1;
                if (it < 15) {
                    issue(s ^ 1);
                    asm volatile("cp.async.wait_group 1;");
                } else {
                    asm volatile("cp.async.wait_group 0;");
                }
                BAR_SYNC(1, 256);

                const float* at = smem + s * STG_FL;
                const float* wt = smem + s * STG_FL + 4608 + role * 1280;

#pragma unroll
                for (int ks = 0; ks < 4; ks++) {
                    const int k0 = ks * 8 + tig;
                    uint32_t af[2][4], bf[2][2];
#pragma unroll
                    for (int mt = 0; mt < 2; mt++) {
                        const int arow = role * 64 + wm * 32 + mt * 16 + g;
                        af[mt][0] = __float_as_uint(at[arow * 36 + k0]);
                        af[mt][1] = __float_as_uint(at[(arow + 8) * 36 + k0]);
                        af[mt][2] = __float_as_uint(at[arow * 36 + k0 + 4]);
                        af[mt][3] = __float_as_uint(at[(arow + 8) * 36 + k0 + 4]);
                    }
#pragma unroll
                    for (int nt = 0; nt < 2; nt++) {
                        const int n0 = wn_ * 16 + nt * 8 + g;
                        bf[nt][0] = __float_as_uint(wt[k0 * 40 + n0]);
                        bf[nt][1] = __float_as_uint(wt[(k0 + 4) * 40 + n0]);
                    }
#pragma unroll
                    for (int mt = 0; mt < 2; mt++)
#pragma unroll
                        for (int nt = 0; nt < 2; nt++) {
                            asm volatile(
                                "mma.sync.aligned.m16n8k8.row.col.f32.tf32.tf32.f32 "
                                "{%0,%1,%2,%3}, {%4,%5,%6,%7}, {%8,%9}, {%0,%1,%2,%3};"
                                : "+f"(c[mt][nt][0]), "+f"(c[mt][nt][1]),
                                  "+f"(c[mt][nt][2]), "+f"(c[mt][nt][3])
                                : "r"(af[mt][0]), "r"(af[mt][1]),
                                  "r"(af[mt][2]), "r"(af[mt][3]),
                                  "r"(bf[nt][0]), "r"(bf[nt][1]));
                        }
                }
                BAR_SYNC(1, 256);
            }

            // H1: wait until store warps finished reading C (skip on 1st tile)
            if (!first) BAR_SYNC(2, 512);
            first = false;

            float* Cs = smem + C_OFF;               // 128 x 32, pitch 40
#pragma unroll
            for (int nt = 0; nt < 2; nt++) {
                const int col = wn_ * 16 + nt * 8 + 2 * tig;
                float b0 = 0.0f, b1 = 0.0f;
                if (role == 0) {
                    b0 = bias[fb * 32 + col];
                    b1 = bias[fb * 32 + col + 1];
                }
#pragma unroll
                for (int mt = 0; mt < 2; mt++) {
                    const int row = role * 64 + wm * 32 + mt * 16 + g;
                    float2 v0 = { c[mt][nt][0] + b0, c[mt][nt][1] + b1 };
                    float2 v1 = { c[mt][nt][2] + b0, c[mt][nt][3] + b1 };
                    *(float2*)&Cs[row * 40 + col]       = v0;
                    *(float2*)&Cs[(row + 8) * 40 + col] = v1;
                }
            }
            // H2: publish C (bar.sync = fenced on both sides)
            BAR_SYNC(3, 512);
        }
    } else {
        // ===================== Store group (256 threads) =====================
        const int sw = warp - 8;          // 0..7
        const int fi = lane & 7;          // float4 within 32-f row
        const int uh = lane >> 3;         // 0..3

        float4* out4 = (float4*)out;
        for (int idx = blockIdx.x; idx < NTILES; idx += NCTAS) {
            const int fb = idx & 31;
            const int tb = (idx >> 5) & 3;
            const int b  = idx >> 7;

            BAR_SYNC(3, 512);              // H2: wait for published C
            const float4* C4 = (const float4*)(smem + C_OFF);   // pitch 10

            float4 lreg[2];
#pragma unroll
            for (int i = 0; i < 2; i++) {
                const int u = sw * 8 + i * 4 + uh;
                lreg[i] = C4[(64 + u) * 10 + fi];
            }

            const size_t row0 = ((size_t)(b * Tn + tb * 64) * Un) * (Fn / 4)
                                + fb * 8 + fi;
#pragma unroll 2
            for (int tt = 0; tt < 64; ++tt) {
                const float4 a = C4[tt * 10 + fi];
                const size_t tbase = row0 + (size_t)tt * Un * (Fn / 4);
#pragma unroll
                for (int i = 0; i < 2; i++) {
                    const int u = sw * 8 + i * 4 + uh;
                    float4 v = { a.x + lreg[i].x, a.y + lreg[i].y,
                                 a.z + lreg[i].z, a.w + lreg[i].w };
                    __stcs(out4 + tbase + (size_t)u * (Fn / 4), v);
                }
            }
            // H1: signal done reading (skip after the last tile)
            if (idx + NCTAS < NTILES) BAR_SYNC(2, 512);
        }
    }
}

// ---------------------------------------------------------------------------
extern "C" void kernel_launch(void* const* d_in, const int* in_sizes, int n_in,
                              void* d_out, int out_size)
{
    const float* audio = (const float*)d_in[0];   // (8,256,512)
    const float* label = (const float*)d_in[1];   // (8,64,512)
    const float* W     = (const float*)d_in[2];   // (1024,1024)
    const float* bias  = (const float*)d_in[3];   // (1024,)
    float* out = (float*)d_out;                   // (8,256,64,1024)

    cudaFuncSetAttribute(joint_fused,
                         cudaFuncAttributeMaxDynamicSharedMemorySize, SMEM_BYTES);

    prep_kernel<<<2304, 256>>>(audio, label, W);
    joint_fused<<<NCTAS, 512, SMEM_BYTES>>>(bias, out);
}